// round 5
// baseline (speedup 1.0000x reference)
#include <cuda_runtime.h>

#define FULLMASK 0xFFFFFFFFu

constexpr int   G     = 64;          // 64x64 grid of 16px cells
constexpr float CELL  = 16.0f;
constexpr float CELLI = 1.0f / 16.0f;
constexpr int   NC    = G * G;
constexpr int   CAP   = 64;          // lambda=16 -> P(cell>64) ~ 1e-19
constexpr int   K     = 9;
constexpr int   TPB   = 4;           // targets per block
constexpr int   WARPS = TPB * 2;     // 2 warps per target
constexpr int   CHUNK = 4;

__device__ int    g_count[NC];
__device__ float4 g_cells[NC * CAP]; // x, y, bitcast(orig idx), pad

__global__ void bin_k(const float* __restrict__ p, int N) {
    int i = blockIdx.x * blockDim.x + threadIdx.x;
    if (i >= N) return;
    float2 c = reinterpret_cast<const float2*>(p)[i * 3 + 1];  // floats 6i+2, 6i+3
    int cx = min(G - 1, max(0, (int)(c.x * CELLI)));
    int cy = min(G - 1, max(0, (int)(c.y * CELLI)));
    int cell = cy * G + cx;
    int pos = atomicAdd(&g_count[cell], 1);
    if (pos < CAP)
        g_cells[cell * CAP + pos] = make_float4(c.x, c.y, __int_as_float(i), 0.f);
}

__global__ __launch_bounds__(WARPS * 32)
void atss_search_k(const float* __restrict__ pbox,
                   const float* __restrict__ tgt,
                   float* __restrict__ out, int NT)
{
    __shared__ unsigned long long sKeys[TPB][18];  // two sorted 9-lists per target
    __shared__ unsigned long long sSel[TPB][K];    // combined sorted top-9

    const int lane = threadIdx.x & 31;
    const int wid  = threadIdx.x >> 5;
    const int pair = wid >> 1;     // target slot within block
    const int half = wid & 1;      // 0 / 1 scan half
    const int t    = blockIdx.x * TPB + pair;
    const bool act = (t < NT);

    const float INF = __int_as_float(0x7f800000);
    float tx = 0.f, ty = 0.f;
    if (act) { tx = tgt[t * 6 + 2]; ty = tgt[t * 6 + 3]; }
    const int tcx = min(G - 1, max(0, (int)(tx * CELLI)));
    const int tcy = min(G - 1, max(0, (int)(ty * CELLI)));

    // per-lane top-K sorted ascending by (d2, idx)
    float bd[K]; int bi[K];
    #pragma unroll
    for (int j = 0; j < K; j++) { bd[j] = INF; bi[j] = 0x7fffffff; }

    auto insertPt = [&](float4 c) {
        float dx = tx - c.x;
        float dy = ty - c.y;
        float d2 = fmaf(dy, dy, dx * dx);      // identical fp expr to verified kernels
        int   ci = __float_as_int(c.z);
        if (d2 < bd[K - 1] || (d2 == bd[K - 1] && ci < bi[K - 1])) {
            float cd = d2; int cj = ci;
            #pragma unroll
            for (int j = 0; j < K; j++) {
                bool lt = (cd < bd[j]) || (cd == bd[j] && cj < bi[j]);
                if (lt) {
                    float td = bd[j]; bd[j] = cd; cd = td;
                    int   ti = bi[j]; bi[j] = cj; cj = ti;
                }
            }
        }
    };

    // ---- split 3x3 fast path: this warp scans virtual indices v = half*32+lane (+64k)
    if (act) {
        int cb[9]; int cnt[9];
        #pragma unroll
        for (int j = 0; j < 9; j++) {
            int x = tcx + (j % 3) - 1;
            int y = tcy + (j / 3) - 1;
            bool ok = (x >= 0) & (x < G) & (y >= 0) & (y < G);
            int c = ok ? (y * G + x) : 0;
            cb[j]  = c * CAP;
            cnt[j] = ok ? min(__ldg(&g_count[c]), CAP) : 0;   // 9 independent loads
        }
        int pref[10];
        pref[0] = 0;
        #pragma unroll
        for (int j = 0; j < 9; j++) pref[j + 1] = pref[j] + cnt[j];
        const int T = pref[9];

        for (int s = half * 32 + lane; s < T; s += 64 * CHUNK) {
            float4 pts[CHUNK]; bool val[CHUNK];
            #pragma unroll
            for (int c = 0; c < CHUNK; c++) {
                int v = s + c * 64;
                val[c] = (v < T);
                int basei = cb[0], pr = 0;
                #pragma unroll
                for (int jj = 1; jj < 9; jj++) {
                    bool ge = (v >= pref[jj]);
                    basei = ge ? cb[jj]   : basei;
                    pr    = ge ? pref[jj] : pr;
                }
                if (val[c]) pts[c] = __ldg(&g_cells[basei + (v - pr)]);
            }
            #pragma unroll
            for (int c = 0; c < CHUNK; c++)
                if (val[c]) insertPt(pts[c]);
        }

        // redux-based sorted top-9 of this warp's half (exact (d2,idx) lex order)
        float sd[K]; int si[K];
        #pragma unroll
        for (int j = 0; j < K; j++) { sd[j] = bd[j]; si[j] = bi[j]; }
        #pragma unroll
        for (int r = 0; r < K; r++) {
            unsigned hb = __float_as_uint(sd[0]);
            unsigned m1 = __reduce_min_sync(FULLMASK, hb);
            unsigned iv = (hb == m1) ? (unsigned)si[0] : 0xFFFFFFFFu;
            unsigned m2 = __reduce_min_sync(FULLMASK, iv);
            if (lane == r)
                sKeys[pair][half * K + r] = ((unsigned long long)m1 << 32) | m2;
            bool owner = (hb == m1) && ((unsigned)si[0] == m2);  // unique for real keys
            if (owner) {     // sentinel multi-pop harmless (routes to fallback)
                #pragma unroll
                for (int j = 0; j < K - 1; j++) { sd[j] = sd[j + 1]; si[j] = si[j + 1]; }
                sd[K - 1] = INF; si[K - 1] = 0x7fffffff;
            }
        }
    }

    __syncthreads();
    if (!act || half == 1) return;   // warp1 done; no further block syncs

    // ---- warp0: rank-routing merge of the two sorted 9-lists ----
    {
        unsigned long long myk = (lane < 18) ? sKeys[pair][lane] : ~0ull;
        int side = (lane >= K) ? 1 : 0;       // 0 = list A, 1 = list B
        int pos  = side ? lane - K : lane;
        int cnt = 0;
        #pragma unroll
        for (int j = 0; j < K; j++) {
            unsigned long long ok = sKeys[pair][side ? j : K + j];
            // strict total order: (key, side) with A before B on equal keys
            bool less = (ok < myk) || (ok == myk && side == 1);
            cnt += less ? 1 : 0;
        }
        int rank = pos + cnt;
        if (lane < 18 && rank < K) sSel[pair][rank] = myk;
        __syncwarp();
    }

    unsigned long long sel = (lane < K) ? sSel[pair][lane] : ~0ull;
    float D9 = __uint_as_float((unsigned)(sSel[pair][K - 1] >> 32));

    // r=1 stop bound: distance from target to edge of scanned 3x3 region
    {
        int x0 = max(tcx - 1, 0), x1 = min(tcx + 1, G - 1);
        int y0 = max(tcy - 1, 0), y1 = min(tcy + 1, G - 1);
        float m = INF;
        if (x0 > 0)     m = fminf(m, tx - (float)x0 * CELL);
        if (x1 < G - 1) m = fminf(m, (float)(x1 + 1) * CELL - tx);
        if (y0 > 0)     m = fminf(m, ty - (float)y0 * CELL);
        if (y1 < G - 1) m = fminf(m, (float)(y1 + 1) * CELL - ty);
        m *= 0.999f;    // conservative margin; false on NaN/INF D9 -> fallback
        bool stop = (m > 0.f && m * m > D9);

        if (!stop) {
            // ---- exact full fallback, warp0 alone (cold; verified ring machinery) ----
            #pragma unroll
            for (int j = 0; j < K; j++) { bd[j] = INF; bi[j] = 0x7fffffff; }

            auto scanCell = [&](int c) {
                int cnt = min(__ldg(&g_count[c]), CAP);
                const float4* base = g_cells + c * CAP;
                for (int i = lane; i < cnt; i += 32)
                    insertPt(__ldg(base + i));
            };
            auto merge = [&]() {
                unsigned long long kk[K];
                #pragma unroll
                for (int j = 0; j < K; j++)
                    kk[j] = ((unsigned long long)__float_as_uint(bd[j]) << 32) | (unsigned)bi[j];
                unsigned long long cur = kk[0];
                #pragma unroll
                for (int r = 0; r < K; r++) {
                    unsigned long long mm = cur;
                    #pragma unroll
                    for (int o = 16; o; o >>= 1) {
                        unsigned long long v = __shfl_xor_sync(FULLMASK, mm, o);
                        if (v < mm) mm = v;
                    }
                    if (lane == r) sel = mm;
                    if (cur == mm) {
                        #pragma unroll
                        for (int j = 0; j < K - 1; j++) kk[j] = kk[j + 1];
                        kk[K - 1] = ~0ull;
                        cur = kk[0];
                    }
                }
            };

            int scanned = 0;
            for (int r = 1; ; r++) {
                int x0b = max(tcx - r, 0), x1b = min(tcx + r, G - 1);
                int y0b = max(tcy - r, 0), y1b = min(tcy + r, G - 1);
                for (int y = y0b; y <= y1b; y++) {
                    bool innerRow = (scanned >= 1) && (y >= tcy - scanned) && (y <= tcy + scanned);
                    if (!innerRow) {
                        for (int x = x0b; x <= x1b; x++) scanCell(y * G + x);
                    } else {
                        if (tcx - r >= 0)     scanCell(y * G + (tcx - r));
                        if (tcx + r <= G - 1) scanCell(y * G + (tcx + r));
                    }
                }
                scanned = r;
                if (x0b == 0 && y0b == 0 && x1b == G - 1 && y1b == G - 1) { merge(); break; }
                merge();
                unsigned d9b = __shfl_sync(FULLMASK, (unsigned)(sel >> 32), 8);
                float D9f = __uint_as_float(d9b);
                float mf = INF;
                if (x0b > 0)     mf = fminf(mf, tx - (float)x0b * CELL);
                if (x1b < G - 1) mf = fminf(mf, (float)(x1b + 1) * CELL - tx);
                if (y0b > 0)     mf = fminf(mf, ty - (float)y0b * CELL);
                if (y1b < G - 1) mf = fminf(mf, (float)(y1b + 1) * CELL - ty);
                mf *= 0.999f;
                if (mf > 0.f && mf * mf > D9f) break;
            }
        }
    }

    // ---- epilogue: GIoU + mean/var(ddof=1) threshold (bit-identical to verified) ----
    float gx = tx, gy = ty;
    float gw = tgt[t * 6 + 4], gh = tgt[t * 6 + 5];

    float cx = 0.f, cy = 0.f, cw_ = 0.f, ch_ = 0.f;
    if (lane < K) {
        int idx = (int)(sel & 0xffffffffull);
        const float* bp = pbox + (size_t)idx * 6;
        cx = bp[2]; cy = bp[3]; cw_ = bp[4]; ch_ = bp[5];
    }

    float b1x1 = gx - gw * 0.5f, b1x2 = gx + gw * 0.5f;
    float b1y1 = gy - gh * 0.5f, b1y2 = gy + gh * 0.5f;
    float b2x1 = cx - cw_ * 0.5f, b2x2 = cx + cw_ * 0.5f;
    float b2y1 = cy - ch_ * 0.5f, b2y2 = cy + ch_ * 0.5f;
    float iw = fmaxf(fminf(b1x2, b2x2) - fmaxf(b1x1, b2x1), 0.f);
    float ih = fmaxf(fminf(b1y2, b2y2) - fmaxf(b1y1, b2y1), 0.f);
    float inter = iw * ih;
    float w1 = b1x2 - b1x1, h1 = b1y2 - b1y1;
    float w2 = b2x2 - b2x1, h2 = b2y2 - b2y1;
    float uni = ((w1 * h1 + 1e-16f) + w2 * h2) - inter;
    float iou = __fdiv_rn(inter, uni);
    float ccw = fmaxf(b1x2, b2x2) - fminf(b1x1, b2x1);
    float cch = fmaxf(b1y2, b2y2) - fminf(b1y1, b2y1);
    float carea = ccw * cch + 1e-16f;
    float g = iou - __fdiv_rn(carea - uni, carea);

    float s = 0.f;
    #pragma unroll
    for (int j = 0; j < K; j++) s += __shfl_sync(FULLMASK, g, j);
    float mean = __fdiv_rn(s, 9.0f);
    float v = 0.f;
    #pragma unroll
    for (int j = 0; j < K; j++) {
        float gj = __shfl_sync(FULLMASK, g, j);
        float d = gj - mean;
        v += d * d;
    }
    float var = __fdiv_rn(v, 8.0f);
    float thr = mean + var;

    if (lane < K) {
        float msk = (g > thr) ? 1.0f : 0.0f;
        float4 o = make_float4(cx * msk, cy * msk, cw_ * msk, ch_ * msk);
        *reinterpret_cast<float4*>(out + ((size_t)t * K + lane) * 4) = o;
    }
}

extern "C" void kernel_launch(void* const* d_in, const int* in_sizes, int n_in,
                              void* d_out, int out_size) {
    const float* pbox = (const float*)d_in[0];
    const float* tgt  = (const float*)d_in[1];
    int N  = in_sizes[0] / 6;
    int NT = in_sizes[1] / 6;

    void* cnt_ptr = nullptr;
    cudaGetSymbolAddress(&cnt_ptr, g_count);
    cudaMemsetAsync(cnt_ptr, 0, NC * sizeof(int));   // memset node, graph-capturable

    bin_k<<<(N + 255) / 256, 256>>>(pbox, N);

    int blocks = (NT + TPB - 1) / TPB;
    atss_search_k<<<blocks, WARPS * 32>>>(pbox, tgt, (float*)d_out, NT);
}

// round 6
// speedup vs baseline: 1.1171x; 1.1171x over previous
#include <cuda_runtime.h>

#define FULLMASK 0xFFFFFFFFu

constexpr int   G     = 64;          // 64x64 grid of 16px cells
constexpr float CELL  = 16.0f;
constexpr float CELLI = 1.0f / 16.0f;
constexpr int   NC    = G * G;
constexpr int   CAP   = 64;          // lambda=16 -> P(cell>64) ~ 1e-19
constexpr int   K     = 9;
constexpr int   WARPS = 4;           // 1 warp per target, small blocks for packing
constexpr int   CHUNK = 5;           // 5*32 = 160 >= typical T (~150)

__device__ int    g_count[NC];
__device__ float4 g_cells[NC * CAP]; // x, y, bitcast(orig idx), pad

__global__ void bin_k(const float* __restrict__ p, int N) {
    int i = blockIdx.x * blockDim.x + threadIdx.x;
    if (i >= N) return;
    float2 c = reinterpret_cast<const float2*>(p)[i * 3 + 1];  // floats 6i+2, 6i+3
    int cx = min(G - 1, max(0, (int)(c.x * CELLI)));
    int cy = min(G - 1, max(0, (int)(c.y * CELLI)));
    int cell = cy * G + cx;
    int pos = atomicAdd(&g_count[cell], 1);
    if (pos < CAP)
        g_cells[cell * CAP + pos] = make_float4(c.x, c.y, __int_as_float(i), 0.f);
}

__global__ __launch_bounds__(WARPS * 32, 6)
void atss_search_k(const float* __restrict__ pbox,
                   const float* __restrict__ tgt,
                   float* __restrict__ out, int NT)
{
    const int lane = threadIdx.x & 31;
    const int t = blockIdx.x * WARPS + (threadIdx.x >> 5);
    if (t >= NT) return;

    const float INF = __int_as_float(0x7f800000);
    // two aligned 8-byte loads: floats (6t+2,6t+3) and (6t+4,6t+5)
    float2 tc = *reinterpret_cast<const float2*>(tgt + t * 6 + 2);
    float2 ts = *reinterpret_cast<const float2*>(tgt + t * 6 + 4);
    const float tx = tc.x, ty = tc.y;
    const int tcx = min(G - 1, max(0, (int)(tx * CELLI)));
    const int tcy = min(G - 1, max(0, (int)(ty * CELLI)));

    // per-lane top-K sorted ascending by (d2, idx)
    float bd[K]; int bi[K];
    #pragma unroll
    for (int j = 0; j < K; j++) { bd[j] = INF; bi[j] = 0x7fffffff; }

    auto insertPt = [&](float4 c) {
        float dx = tx - c.x;
        float dy = ty - c.y;
        float d2 = fmaf(dy, dy, dx * dx);      // identical fp expr to verified kernels
        int   ci = __float_as_int(c.z);
        // order-independent (d2, idx) lexicographic selection
        if (d2 < bd[K - 1] || (d2 == bd[K - 1] && ci < bi[K - 1])) {
            float cd = d2; int cj = ci;
            #pragma unroll
            for (int j = 0; j < K; j++) {
                bool lt = (cd < bd[j]) || (cd == bd[j] && cj < bi[j]);
                if (lt) {
                    float td = bd[j]; bd[j] = cd; cd = td;
                    int   ti = bi[j]; bi[j] = cj; cj = ti;
                }
            }
        }
    };

    // ---- fast path: flat-indexed 3x3 scan with batched independent loads ----
    {
        int cb[9]; int cnt[9];
        #pragma unroll
        for (int j = 0; j < 9; j++) {
            int x = tcx + (j % 3) - 1;
            int y = tcy + (j / 3) - 1;
            bool ok = (x >= 0) & (x < G) & (y >= 0) & (y < G);
            int c = ok ? (y * G + x) : 0;
            cb[j]  = c * CAP;
            cnt[j] = ok ? min(__ldg(&g_count[c]), CAP) : 0;   // 9 independent loads
        }
        int pref[10];
        pref[0] = 0;
        #pragma unroll
        for (int j = 0; j < 9; j++) pref[j + 1] = pref[j] + cnt[j];
        const int T = pref[9];

        for (int s = 0; s < T; s += 32 * CHUNK) {
            float4 pts[CHUNK]; bool val[CHUNK];
            #pragma unroll
            for (int c = 0; c < CHUNK; c++) {
                int v = s + c * 32 + lane;
                val[c] = (v < T);
                // map v -> (cell, offset) via unrolled predicated select chain
                int basei = cb[0], pr = 0;
                #pragma unroll
                for (int jj = 1; jj < 9; jj++) {
                    bool ge = (v >= pref[jj]);
                    basei = ge ? cb[jj]   : basei;
                    pr    = ge ? pref[jj] : pr;
                }
                if (val[c]) pts[c] = __ldg(&g_cells[basei + (v - pr)]);  // high MLP
            }
            #pragma unroll
            for (int c = 0; c < CHUNK; c++)
                if (val[c]) insertPt(pts[c]);
        }
    }

    // cold-path cell scan used by ring expansion (r >= 2)
    auto scanCell = [&](int c) {
        int cnt = min(__ldg(&g_count[c]), CAP);
        const float4* base = g_cells + c * CAP;
        for (int i = lane; i < cnt; i += 32)
            insertPt(__ldg(base + i));
    };

    // ordered warp merge: after round r, lane r holds r-th smallest (d2,idx) key
    // (reference top_k order).
    unsigned long long sel = ~0ull;
    auto merge = [&]() {
        unsigned long long kk[K];
        #pragma unroll
        for (int j = 0; j < K; j++)
            kk[j] = ((unsigned long long)__float_as_uint(bd[j]) << 32) | (unsigned)bi[j];
        unsigned long long cur = kk[0];
        #pragma unroll
        for (int r = 0; r < K; r++) {
            unsigned long long m = cur;
            #pragma unroll
            for (int o = 16; o; o >>= 1) {
                unsigned long long v = __shfl_xor_sync(FULLMASK, m, o);
                if (v < m) m = v;
            }
            if (lane == r) sel = m;
            if (cur == m) {          // unique keys -> exactly one owner pops
                #pragma unroll
                for (int j = 0; j < K - 1; j++) kk[j] = kk[j + 1];
                kk[K - 1] = ~0ull;
                cur = kk[0];
            }
        }
    };

    // ring expansion with provable stop bound (cold beyond r=1)
    int done = 1;
    for (int r = 1; ; r++) {
        int x0 = max(tcx - r, 0), x1 = min(tcx + r, G - 1);
        int y0 = max(tcy - r, 0), y1 = min(tcy + r, G - 1);
        if (r > done) {
            for (int y = y0; y <= y1; y++) {
                bool innerRow = (y >= tcy - (r - 1)) && (y <= tcy + (r - 1));
                if (!innerRow) {
                    for (int x = x0; x <= x1; x++) scanCell(y * G + x);
                } else {
                    if (tcx - r >= 0)     scanCell(y * G + (tcx - r));
                    if (tcx + r <= G - 1) scanCell(y * G + (tcx + r));
                }
            }
            done = r;
        }
        if (x0 == 0 && y0 == 0 && x1 == G - 1 && y1 == G - 1) { merge(); break; }
        merge();
        // D9 = d2 of the exact warp 9th-smallest (lane 8); INF/garbage if <9 real -> no stop
        unsigned d9bits = __shfl_sync(FULLMASK, (unsigned)(sel >> 32), 8);
        float D9 = __uint_as_float(d9bits);
        float m = INF;
        if (x0 > 0)     m = fminf(m, tx - (float)x0 * CELL);
        if (x1 < G - 1) m = fminf(m, (float)(x1 + 1) * CELL - tx);
        if (y0 > 0)     m = fminf(m, ty - (float)y0 * CELL);
        if (y1 < G - 1) m = fminf(m, (float)(y1 + 1) * CELL - ty);
        m *= 0.999f;    // conservative margin >> fp rounding; never stops early
        if (m > 0.f && m * m > D9) break;   // false on NaN/INF -> keep expanding
    }

    // ---- epilogue: GIoU + mean/var(ddof=1) threshold (bit-identical fp order) ----
    float gx = tx, gy = ty;
    float gw = ts.x, gh = ts.y;

    float cx = 0.f, cy = 0.f, cw_ = 0.f, ch_ = 0.f;
    if (lane < K) {
        int idx = (int)(sel & 0xffffffffull);
        // aligned 8-byte loads: floats (6i+2,6i+3) at byte 24i+8, (6i+4,6i+5) at 24i+16
        float2 pc = *reinterpret_cast<const float2*>(pbox + (size_t)idx * 6 + 2);
        float2 ps = *reinterpret_cast<const float2*>(pbox + (size_t)idx * 6 + 4);
        cx = pc.x; cy = pc.y; cw_ = ps.x; ch_ = ps.y;
    }

    float b1x1 = gx - gw * 0.5f, b1x2 = gx + gw * 0.5f;
    float b1y1 = gy - gh * 0.5f, b1y2 = gy + gh * 0.5f;
    float b2x1 = cx - cw_ * 0.5f, b2x2 = cx + cw_ * 0.5f;
    float b2y1 = cy - ch_ * 0.5f, b2y2 = cy + ch_ * 0.5f;
    float iw = fmaxf(fminf(b1x2, b2x2) - fmaxf(b1x1, b2x1), 0.f);
    float ih = fmaxf(fminf(b1y2, b2y2) - fmaxf(b1y1, b2y1), 0.f);
    float inter = iw * ih;
    float w1 = b1x2 - b1x1, h1 = b1y2 - b1y1;
    float w2 = b2x2 - b2x1, h2 = b2y2 - b2y1;
    float uni = ((w1 * h1 + 1e-16f) + w2 * h2) - inter;
    float iou = __fdiv_rn(inter, uni);
    float ccw = fmaxf(b1x2, b2x2) - fminf(b1x1, b2x1);
    float cch = fmaxf(b1y2, b2y2) - fminf(b1y1, b2y1);
    float carea = ccw * cch + 1e-16f;
    float g = iou - __fdiv_rn(carea - uni, carea);

    float s = 0.f;
    #pragma unroll
    for (int j = 0; j < K; j++) s += __shfl_sync(FULLMASK, g, j);
    float mean = __fdiv_rn(s, 9.0f);
    float v = 0.f;
    #pragma unroll
    for (int j = 0; j < K; j++) {
        float gj = __shfl_sync(FULLMASK, g, j);
        float d = gj - mean;
        v += d * d;
    }
    float var = __fdiv_rn(v, 8.0f);
    float thr = mean + var;

    if (lane < K) {
        float msk = (g > thr) ? 1.0f : 0.0f;
        float4 o = make_float4(cx * msk, cy * msk, cw_ * msk, ch_ * msk);
        *reinterpret_cast<float4*>(out + ((size_t)t * K + lane) * 4) = o;
    }
}

extern "C" void kernel_launch(void* const* d_in, const int* in_sizes, int n_in,
                              void* d_out, int out_size) {
    const float* pbox = (const float*)d_in[0];
    const float* tgt  = (const float*)d_in[1];
    int N  = in_sizes[0] / 6;
    int NT = in_sizes[1] / 6;

    void* cnt_ptr = nullptr;
    cudaGetSymbolAddress(&cnt_ptr, g_count);
    cudaMemsetAsync(cnt_ptr, 0, NC * sizeof(int));   // memset node, graph-capturable

    bin_k<<<(N + 255) / 256, 256>>>(pbox, N);

    int blocks = (NT + WARPS - 1) / WARPS;
    atss_search_k<<<blocks, WARPS * 32>>>(pbox, tgt, (float*)d_out, NT);
}

// round 7
// speedup vs baseline: 1.2962x; 1.1604x over previous
#include <cuda_runtime.h>

#define FULLMASK 0xFFFFFFFFu

constexpr int   G     = 64;          // 64x64 grid of 16px cells
constexpr float CELL  = 16.0f;
constexpr float CELLI = 1.0f / 16.0f;
constexpr int   NC    = G * G;
constexpr int   CAP   = 64;          // lambda=16 -> P(cell>64) ~ 1e-19
constexpr int   K     = 9;
constexpr int   WARPS = 2;           // small blocks -> better wave balance
constexpr int   CHUNK = 6;           // 6*32 = 192 capacity; P(T>192) ~ 3e-5

__device__ int    g_count[NC];
__device__ float4 g_cells[NC * CAP]; // x, y, bitcast(orig idx), pad

__global__ void bin_k(const float* __restrict__ p, int N) {
    int i = blockIdx.x * blockDim.x + threadIdx.x;
    if (i >= N) return;
    float2 c = reinterpret_cast<const float2*>(p)[i * 3 + 1];  // floats 6i+2, 6i+3
    int cx = min(G - 1, max(0, (int)(c.x * CELLI)));
    int cy = min(G - 1, max(0, (int)(c.y * CELLI)));
    int cell = cy * G + cx;
    int pos = atomicAdd(&g_count[cell], 1);
    if (pos < CAP)
        g_cells[cell * CAP + pos] = make_float4(c.x, c.y, __int_as_float(i), 0.f);
}

__global__ __launch_bounds__(WARPS * 32, 8)
void atss_search_k(const float* __restrict__ pbox,
                   const float* __restrict__ tgt,
                   float* __restrict__ out, int NT)
{
    const int lane = threadIdx.x & 31;
    const int t = blockIdx.x * WARPS + (threadIdx.x >> 5);
    if (t >= NT) return;

    const float INF = __int_as_float(0x7f800000);
    float2 tc = *reinterpret_cast<const float2*>(tgt + t * 6 + 2);
    float2 ts = *reinterpret_cast<const float2*>(tgt + t * 6 + 4);
    const float tx = tc.x, ty = tc.y;
    const int tcx = min(G - 1, max(0, (int)(tx * CELLI)));
    const int tcy = min(G - 1, max(0, (int)(ty * CELLI)));

    // ---- gather 3x3 cell info ----
    int cb[9]; int cnt[9];
    #pragma unroll
    for (int j = 0; j < 9; j++) {
        int x = tcx + (j % 3) - 1;
        int y = tcy + (j / 3) - 1;
        bool ok = (x >= 0) & (x < G) & (y >= 0) & (y < G);
        int c = ok ? (y * G + x) : 0;
        cb[j]  = c * CAP;
        cnt[j] = ok ? min(__ldg(&g_count[c]), CAP) : 0;   // 9 independent loads
    }
    int pref[10];
    pref[0] = 0;
    #pragma unroll
    for (int j = 0; j < 9; j++) pref[j + 1] = pref[j] + cnt[j];
    const int T = pref[9];

    unsigned long long sel = ~0ull;
    bool stop = false;

    if (T <= 32 * CHUNK) {
        // ---- hot path: single-pass load, lane sort, REDUX extraction ----
        unsigned long long key[CHUNK];
        {
            float4 pts[CHUNK]; bool val[CHUNK];
            #pragma unroll
            for (int c = 0; c < CHUNK; c++) {
                int v = c * 32 + lane;
                val[c] = (v < T);
                int basei = cb[0], pr = 0;
                #pragma unroll
                for (int jj = 1; jj < 9; jj++) {
                    bool ge = (v >= pref[jj]);
                    basei = ge ? cb[jj]   : basei;
                    pr    = ge ? pref[jj] : pr;
                }
                if (val[c]) pts[c] = __ldg(&g_cells[basei + (v - pr)]);  // high MLP
            }
            #pragma unroll
            for (int c = 0; c < CHUNK; c++) {
                if (val[c]) {
                    float dx = tx - pts[c].x;
                    float dy = ty - pts[c].y;
                    float d2 = fmaf(dy, dy, dx * dx);   // identical fp expr to verified kernels
                    key[c] = ((unsigned long long)__float_as_uint(d2) << 32)
                           | (unsigned)__float_as_int(pts[c].z);
                } else {
                    key[c] = ~0ull;                     // pad sorts last (> any real d2bits)
                }
            }
        }

        // optimal 12-CE sorting network for 6 elements (ascending)
        auto CE = [&](int a, int b) {
            unsigned long long ka = key[a], kb = key[b];
            key[a] = ka < kb ? ka : kb;
            key[b] = ka < kb ? kb : ka;
        };
        CE(1,2); CE(4,5); CE(0,2); CE(3,5); CE(0,1); CE(3,4);
        CE(2,5); CE(0,3); CE(1,4); CE(2,4); CE(1,3); CE(2,3);

        // 9 extraction rounds: exact lex-min via two hardware REDUX.MIN ops.
        // After round r, (m1,m2) = r-th smallest (d2,idx) pair, broadcast to all lanes.
        unsigned D9bits = 0xFFFFFFFFu;
        #pragma unroll
        for (int r = 0; r < K; r++) {
            unsigned hi = (unsigned)(key[0] >> 32);
            unsigned lo = (unsigned)key[0];
            unsigned m1 = __reduce_min_sync(FULLMASK, hi);
            unsigned iv = (hi == m1) ? lo : 0xFFFFFFFFu;
            unsigned m2 = __reduce_min_sync(FULLMASK, iv);
            if (lane == r) sel = ((unsigned long long)m1 << 32) | m2;
            if (r == K - 1) D9bits = m1;
            if (hi == m1 && lo == m2) {     // unique owner for real keys; pad multi-pop harmless
                #pragma unroll
                for (int j = 0; j < CHUNK - 1; j++) key[j] = key[j + 1];
                key[CHUNK - 1] = ~0ull;
            }
        }

        // r=1 stop bound (conservative). NaN/INF D9 -> stop stays false -> fallback.
        float D9 = __uint_as_float(D9bits);
        int x0 = max(tcx - 1, 0), x1 = min(tcx + 1, G - 1);
        int y0 = max(tcy - 1, 0), y1 = min(tcy + 1, G - 1);
        float m = INF;
        if (x0 > 0)     m = fminf(m, tx - (float)x0 * CELL);
        if (x1 < G - 1) m = fminf(m, (float)(x1 + 1) * CELL - tx);
        if (y0 > 0)     m = fminf(m, ty - (float)y0 * CELL);
        if (y1 < G - 1) m = fminf(m, (float)(y1 + 1) * CELL - ty);
        m *= 0.999f;
        stop = (m > 0.f && m * m > D9);
    }

    if (!stop) {
        // ---- exact fallback from scratch (cold; verified ring machinery) ----
        float bd[K]; int bi[K];
        #pragma unroll
        for (int j = 0; j < K; j++) { bd[j] = INF; bi[j] = 0x7fffffff; }

        auto insertPt = [&](float4 c) {
            float dx = tx - c.x;
            float dy = ty - c.y;
            float d2 = fmaf(dy, dy, dx * dx);
            int   ci = __float_as_int(c.z);
            if (d2 < bd[K - 1] || (d2 == bd[K - 1] && ci < bi[K - 1])) {
                float cd = d2; int cj = ci;
                #pragma unroll
                for (int j = 0; j < K; j++) {
                    bool lt = (cd < bd[j]) || (cd == bd[j] && cj < bi[j]);
                    if (lt) {
                        float td = bd[j]; bd[j] = cd; cd = td;
                        int   ti = bi[j]; bi[j] = cj; cj = ti;
                    }
                }
            }
        };
        auto scanCell = [&](int c) {
            int cc = min(__ldg(&g_count[c]), CAP);
            const float4* base = g_cells + c * CAP;
            for (int i = lane; i < cc; i += 32)
                insertPt(__ldg(base + i));
        };
        auto merge = [&]() {
            unsigned long long kk[K];
            #pragma unroll
            for (int j = 0; j < K; j++)
                kk[j] = ((unsigned long long)__float_as_uint(bd[j]) << 32) | (unsigned)bi[j];
            unsigned long long cur = kk[0];
            #pragma unroll
            for (int r = 0; r < K; r++) {
                unsigned long long mm = cur;
                #pragma unroll
                for (int o = 16; o; o >>= 1) {
                    unsigned long long v = __shfl_xor_sync(FULLMASK, mm, o);
                    if (v < mm) mm = v;
                }
                if (lane == r) sel = mm;
                if (cur == mm) {
                    #pragma unroll
                    for (int j = 0; j < K - 1; j++) kk[j] = kk[j + 1];
                    kk[K - 1] = ~0ull;
                    cur = kk[0];
                }
            }
        };

        int scanned = -1;     // nothing scanned yet: rescan everything from scratch
        for (int r = 1; ; r++) {
            int x0 = max(tcx - r, 0), x1 = min(tcx + r, G - 1);
            int y0 = max(tcy - r, 0), y1 = min(tcy + r, G - 1);
            for (int y = y0; y <= y1; y++) {
                bool innerRow = (scanned >= 0) && (y >= tcy - scanned) && (y <= tcy + scanned);
                if (!innerRow) {
                    for (int x = x0; x <= x1; x++) scanCell(y * G + x);
                } else {
                    int lx = tcx - scanned - 1;
                    for (int x = max(lx - (r - 1 - scanned), x0); x <= lx && x >= x0; x++)
                        scanCell(y * G + x);
                    int rx = tcx + scanned + 1;
                    for (int x = rx; x <= min(rx + (r - 1 - scanned), x1); x++)
                        scanCell(y * G + x);
                }
            }
            scanned = r;
            if (x0 == 0 && y0 == 0 && x1 == G - 1 && y1 == G - 1) { merge(); break; }
            merge();
            unsigned d9b = __shfl_sync(FULLMASK, (unsigned)(sel >> 32), 8);
            float D9f = __uint_as_float(d9b);
            float mf = INF;
            if (x0 > 0)     mf = fminf(mf, tx - (float)x0 * CELL);
            if (x1 < G - 1) mf = fminf(mf, (float)(x1 + 1) * CELL - tx);
            if (y0 > 0)     mf = fminf(mf, ty - (float)y0 * CELL);
            if (y1 < G - 1) mf = fminf(mf, (float)(y1 + 1) * CELL - ty);
            mf *= 0.999f;
            if (mf > 0.f && mf * mf > D9f) break;
        }
    }

    // ---- epilogue: GIoU + mean/var(ddof=1) threshold (bit-identical fp order) ----
    float gx = tx, gy = ty;
    float gw = ts.x, gh = ts.y;

    float cx = 0.f, cy = 0.f, cw_ = 0.f, ch_ = 0.f;
    if (lane < K) {
        int idx = (int)(sel & 0xffffffffull);
        float2 pc = *reinterpret_cast<const float2*>(pbox + (size_t)idx * 6 + 2);
        float2 ps = *reinterpret_cast<const float2*>(pbox + (size_t)idx * 6 + 4);
        cx = pc.x; cy = pc.y; cw_ = ps.x; ch_ = ps.y;
    }

    float b1x1 = gx - gw * 0.5f, b1x2 = gx + gw * 0.5f;
    float b1y1 = gy - gh * 0.5f, b1y2 = gy + gh * 0.5f;
    float b2x1 = cx - cw_ * 0.5f, b2x2 = cx + cw_ * 0.5f;
    float b2y1 = cy - ch_ * 0.5f, b2y2 = cy + ch_ * 0.5f;
    float iw = fmaxf(fminf(b1x2, b2x2) - fmaxf(b1x1, b2x1), 0.f);
    float ih = fmaxf(fminf(b1y2, b2y2) - fmaxf(b1y1, b2y1), 0.f);
    float inter = iw * ih;
    float w1 = b1x2 - b1x1, h1 = b1y2 - b1y1;
    float w2 = b2x2 - b2x1, h2 = b2y2 - b2y1;
    float uni = ((w1 * h1 + 1e-16f) + w2 * h2) - inter;
    float iou = __fdiv_rn(inter, uni);
    float ccw = fmaxf(b1x2, b2x2) - fminf(b1x1, b2x1);
    float cch = fmaxf(b1y2, b2y2) - fminf(b1y1, b2y1);
    float carea = ccw * cch + 1e-16f;
    float g = iou - __fdiv_rn(carea - uni, carea);

    float s = 0.f;
    #pragma unroll
    for (int j = 0; j < K; j++) s += __shfl_sync(FULLMASK, g, j);
    float mean = __fdiv_rn(s, 9.0f);
    float v = 0.f;
    #pragma unroll
    for (int j = 0; j < K; j++) {
        float gj = __shfl_sync(FULLMASK, g, j);
        float d = gj - mean;
        v += d * d;
    }
    float var = __fdiv_rn(v, 8.0f);
    float thr = mean + var;

    if (lane < K) {
        float msk = (g > thr) ? 1.0f : 0.0f;
        float4 o = make_float4(cx * msk, cy * msk, cw_ * msk, ch_ * msk);
        *reinterpret_cast<float4*>(out + ((size_t)t * K + lane) * 4) = o;
    }
}

extern "C" void kernel_launch(void* const* d_in, const int* in_sizes, int n_in,
                              void* d_out, int out_size) {
    const float* pbox = (const float*)d_in[0];
    const float* tgt  = (const float*)d_in[1];
    int N  = in_sizes[0] / 6;
    int NT = in_sizes[1] / 6;

    void* cnt_ptr = nullptr;
    cudaGetSymbolAddress(&cnt_ptr, g_count);
    cudaMemsetAsync(cnt_ptr, 0, NC * sizeof(int));   // memset node, graph-capturable

    bin_k<<<(N + 255) / 256, 256>>>(pbox, N);

    int blocks = (NT + WARPS - 1) / WARPS;
    atss_search_k<<<blocks, WARPS * 32>>>(pbox, tgt, (float*)d_out, NT);
}